// round 1
// baseline (speedup 1.0000x reference)
#include <cuda_runtime.h>
#include <cstdint>
#include <cstddef>

#define Bz 8192
#define Nz 64
#define Dz 256
#define Hz 8
#define HHz 32
#define KTOT (Hz*Dz) /* 2048 */

// ---------------- scratch (static device globals; no allocations) ----------
__device__ float g_wnb[Hz*Dz];            // 8KB
__device__ float g_wcur[Hz*Dz];           // 8KB
__device__ float g_M2[(size_t)KTOT*Dz];   // 2MB   [k][e], k = h*256+d
__device__ float g_G[(size_t)Bz*KTOT];    // 64MB  [b][h*256+d]

// ---------------- packed f32x2 helpers (FFMA2) -----------------------------
__device__ __forceinline__ unsigned long long pack2(float x, float y){
    unsigned long long r;
    asm("mov.b64 %0, {%1, %2};" : "=l"(r) : "f"(x), "f"(y));
    return r;
}
__device__ __forceinline__ void fma2(unsigned long long &acc, unsigned long long a, unsigned long long b){
    asm("fma.rn.f32x2 %0, %1, %2, %0;" : "+l"(acc) : "l"(a), "l"(b));
}
__device__ __forceinline__ float2 unpack2(unsigned long long v){
    float lo, hi;
    asm("mov.b64 {%0, %1}, %2;" : "=f"(lo), "=f"(hi) : "l"(v));
    return make_float2(lo, hi);
}

// ---------------- K1a: wcur[h,:], wnb[h,:] ---------------------------------
__global__ void prep_vecs_kernel(const float* __restrict__ W,
                                 const float* __restrict__ cur_a,
                                 const float* __restrict__ nb_a){
    int h = blockIdx.x, d = threadIdx.x;
    float sc = 0.f, sn = 0.f;
    #pragma unroll
    for (int j = 0; j < HHz; j++){
        float w = W[(h*HHz + j)*Dz + d];
        sc += cur_a[h*HHz + j] * w;
        sn += nb_a [h*HHz + j] * w;
    }
    g_wcur[h*Dz + d] = sc;
    g_wnb [h*Dz + d] = sn;
}

// ---------------- K1b: M2[(h,d),e] = sum_j W[h*32+j,d]*W_out[e,h*32+j] -----
__global__ void prep_M2_kernel(const float* __restrict__ W,
                               const float* __restrict__ W_out){
    int k = blockIdx.x;              // 0..2047
    int h = k >> 8, d = k & 255;
    __shared__ float sW[HHz];
    int t = threadIdx.x;             // e = t
    if (t < HHz) sW[t] = W[(h*HHz + t)*Dz + d];
    __syncthreads();
    float acc = 0.f;
    const float* wo = W_out + (size_t)t*Dz + h*HHz;
    #pragma unroll
    for (int j = 0; j < HHz; j++) acc += sW[j] * wo[j];
    g_M2[(size_t)k*Dz + t] = acc;
}

// ---------------- K2: fused attention per batch ----------------------------
// grid = 8192, block = 256 (8 warps). smem: inter tile 64KB + scores/attn.
#define SMEM_ATTN ((Nz*Dz + Nz*Hz + Nz*Hz) * 4)

__global__ __launch_bounds__(256, 3)
void attn_kernel(const float* __restrict__ inter,
                 const int*   __restrict__ lengths,
                 float*       __restrict__ out){
    extern __shared__ float smem[];
    float* s_inter = smem;                 // [64][256]
    float* s_nb    = smem + Nz*Dz;         // [64][8]
    float* s_attn  = s_nb + Nz*Hz;         // [64][8]

    int b = blockIdx.x;
    int t = threadIdx.x;
    int w = t >> 5, l = t & 31;

    // ---- load inter_info[b] tile (64x256 f32, coalesced float4) ----
    const float4* src = (const float4*)(inter + (size_t)b*Nz*Dz);
    float4* dst = (float4*)s_inter;
    #pragma unroll
    for (int i = 0; i < 16; i++) dst[t + 256*i] = src[t + 256*i];

    // ---- wnb register tile: warp covers 4 heads x (n quarter) ----
    int hbase = (w >> 2) << 2;   // 0 or 4
    int nq    = w & 3;           // n in [nq*16, nq*16+16)
    float wnbr[4][8];
    #pragma unroll
    for (int hi = 0; hi < 4; hi++)
        #pragma unroll
        for (int k = 0; k < 8; k++)
            wnbr[hi][k] = g_wnb[(hbase + hi)*Dz + l + 32*k];
    __syncthreads();

    // ---- nb scores: dot(inter[n,:], wnb[h,:]) ----
    for (int n = nq*16; n < nq*16 + 16; n++){
        float p0 = 0.f, p1 = 0.f, p2 = 0.f, p3 = 0.f;
        #pragma unroll
        for (int k = 0; k < 8; k++){
            float x = s_inter[n*Dz + l + 32*k];
            p0 += x * wnbr[0][k];
            p1 += x * wnbr[1][k];
            p2 += x * wnbr[2][k];
            p3 += x * wnbr[3][k];
        }
        #pragma unroll
        for (int off = 16; off > 0; off >>= 1){
            p0 += __shfl_xor_sync(0xffffffffu, p0, off);
            p1 += __shfl_xor_sync(0xffffffffu, p1, off);
            p2 += __shfl_xor_sync(0xffffffffu, p2, off);
            p3 += __shfl_xor_sync(0xffffffffu, p3, off);
        }
        if (l == 0){
            s_nb[n*Hz + hbase + 0] = p0;
            s_nb[n*Hz + hbase + 1] = p1;
            s_nb[n*Hz + hbase + 2] = p2;
            s_nb[n*Hz + hbase + 3] = p3;
        }
    }
    __syncthreads();

    // ---- cur score + leaky + mask + softmax: warp w owns head h = w ----
    {
        int h = w;
        float c = 0.f;
        #pragma unroll
        for (int k = 0; k < 8; k++)
            c += s_inter[l + 32*k] * g_wcur[h*Dz + l + 32*k];
        #pragma unroll
        for (int off = 16; off > 0; off >>= 1)
            c += __shfl_xor_sync(0xffffffffu, c, off);

        int len = lengths[b]; if (len < 1) len = 1;

        float v0 = c + s_nb[l*Hz + h];
        float v1 = c + s_nb[(l + 32)*Hz + h];
        v0 = v0 > 0.f ? v0 : 0.01f*v0;
        v1 = v1 > 0.f ? v1 : 0.01f*v1;
        bool m0 = (l < len), m1 = ((l + 32) < len);
        float y0 = m0 ? v0 : -3.0e38f;
        float y1 = m1 ? v1 : -3.0e38f;
        float mx = fmaxf(y0, y1);
        #pragma unroll
        for (int off = 16; off > 0; off >>= 1)
            mx = fmaxf(mx, __shfl_xor_sync(0xffffffffu, mx, off));
        float e0 = m0 ? __expf(v0 - mx) : 0.f;
        float e1 = m1 ? __expf(v1 - mx) : 0.f;
        float s = e0 + e1;
        #pragma unroll
        for (int off = 16; off > 0; off >>= 1)
            s += __shfl_xor_sync(0xffffffffu, s, off);
        float inv = 1.f / s;
        s_attn[l*Hz + h]        = e0 * inv;
        s_attn[(l + 32)*Hz + h] = e1 * inv;
    }
    __syncthreads();

    // ---- G[b,h,d] = sum_n attn[n,h] * inter[n,d]; also copy query row ----
    {
        int d = t;
        float acc[8];
        #pragma unroll
        for (int h = 0; h < 8; h++) acc[h] = 0.f;
        #pragma unroll 4
        for (int n = 0; n < Nz; n++){
            float4 a0 = *(float4*)(s_attn + n*Hz);
            float4 a1 = *(float4*)(s_attn + n*Hz + 4);
            float x = s_inter[n*Dz + d];
            acc[0] += a0.x*x; acc[1] += a0.y*x; acc[2] += a0.z*x; acc[3] += a0.w*x;
            acc[4] += a1.x*x; acc[5] += a1.y*x; acc[6] += a1.z*x; acc[7] += a1.w*x;
        }
        float* Gp = g_G + (size_t)b*KTOT;
        #pragma unroll
        for (int h = 0; h < 8; h++) Gp[h*Dz + d] = acc[h];
        // batch_query_info = inter_info[:,0]
        out[(size_t)Bz*Dz + (size_t)b*Dz + d] = s_inter[d];
    }
}

// ---------------- K3: out1 = G (8192x2048) @ M2 (2048x256) -----------------
#define BM 128
#define BN 128
#define KC 16

__global__ __launch_bounds__(256)
void out_gemm_kernel(float* __restrict__ out){
    __shared__ float Gs[KC][BM + 4];   // +4 keeps float4 alignment (528B rows)
    __shared__ float Ms[KC][BN];

    int t  = threadIdx.x;
    int tx = t & 15, ty = t >> 4;
    int row0 = blockIdx.x * BM;
    int col0 = blockIdx.y * BN;

    unsigned long long acc2[8][4];
    #pragma unroll
    for (int i = 0; i < 8; i++)
        #pragma unroll
        for (int j = 0; j < 4; j++) acc2[i][j] = 0ull;

    const float* Gbase = g_G + (size_t)row0*KTOT;
    int lr = t >> 1;          // G row within tile (0..127)
    int lk = (t & 1) * 8;     // k offset (0 or 8)
    int mk = t >> 4;          // M2 k row (0..15)
    int mc = (t & 15) * 8;    // M2 col offset

    for (int k0 = 0; k0 < KTOT; k0 += KC){
        const float* gp = Gbase + (size_t)lr*KTOT + k0 + lk;
        float4 v0 = *(const float4*)gp;
        float4 v1 = *(const float4*)(gp + 4);
        Gs[lk+0][lr] = v0.x; Gs[lk+1][lr] = v0.y; Gs[lk+2][lr] = v0.z; Gs[lk+3][lr] = v0.w;
        Gs[lk+4][lr] = v1.x; Gs[lk+5][lr] = v1.y; Gs[lk+6][lr] = v1.z; Gs[lk+7][lr] = v1.w;
        const float* mp = g_M2 + (size_t)(k0 + mk)*Dz + col0 + mc;
        *(float4*)&Ms[mk][mc]     = *(const float4*)mp;
        *(float4*)&Ms[mk][mc + 4] = *(const float4*)(mp + 4);
        __syncthreads();

        #pragma unroll
        for (int kk = 0; kk < KC; kk++){
            float4 a0 = *(float4*)&Gs[kk][ty*8];
            float4 a1 = *(float4*)&Gs[kk][ty*8 + 4];
            ulonglong2 b0 = *(ulonglong2*)&Ms[kk][tx*8];
            ulonglong2 b1 = *(ulonglong2*)&Ms[kk][tx*8 + 4];
            float a[8] = {a0.x, a0.y, a0.z, a0.w, a1.x, a1.y, a1.z, a1.w};
            unsigned long long bb[4] = {b0.x, b0.y, b1.x, b1.y};
            #pragma unroll
            for (int i = 0; i < 8; i++){
                unsigned long long ai2 = pack2(a[i], a[i]);
                #pragma unroll
                for (int j = 0; j < 4; j++) fma2(acc2[i][j], ai2, bb[j]);
            }
        }
        __syncthreads();
    }

    #pragma unroll
    for (int i = 0; i < 8; i++){
        float4 r0, r1; float2 p;
        p = unpack2(acc2[i][0]); r0.x = p.x; r0.y = p.y;
        p = unpack2(acc2[i][1]); r0.z = p.x; r0.w = p.y;
        p = unpack2(acc2[i][2]); r1.x = p.x; r1.y = p.y;
        p = unpack2(acc2[i][3]); r1.z = p.x; r1.w = p.y;
        float* op = out + (size_t)(row0 + ty*8 + i)*Dz + col0 + tx*8;
        *(float4*)op       = r0;
        *(float4*)(op + 4) = r1;
    }
}

// ---------------- launch ----------------------------------------------------
extern "C" void kernel_launch(void* const* d_in, const int* in_sizes, int n_in,
                              void* d_out, int out_size){
    const float* inter   = (const float*)d_in[0];
    const int*   lengths = (const int*)  d_in[1];
    const float* W       = (const float*)d_in[2];
    const float* cur_a   = (const float*)d_in[3];
    const float* nb_a    = (const float*)d_in[4];
    const float* W_out   = (const float*)d_in[5];
    float* out = (float*)d_out;

    cudaFuncSetAttribute(attn_kernel, cudaFuncAttributeMaxDynamicSharedMemorySize, SMEM_ATTN);

    prep_vecs_kernel<<<Hz, Dz>>>(W, cur_a, nb_a);
    prep_M2_kernel<<<KTOT, Dz>>>(W, W_out);
    attn_kernel<<<Bz, 256, SMEM_ATTN>>>(inter, lengths, out);
    dim3 g3(Bz/BM, Dz/BN);
    out_gemm_kernel<<<g3, 256>>>(out);
}